// round 1
// baseline (speedup 1.0000x reference)
#include <cuda_runtime.h>
#include <math.h>

// Problem constants
#define NN 50000
#define GG 64

// ---------------- scratch (static device globals; no allocation) ----------------
__device__ float4 g_xW4[NN * 96];   // N x 384 floats (max HEADS*C = 4*96)
__device__ float4 g_B4[NN * 24];    // N x 96 floats
__device__ float4 g_C4[NN * 24];    // N x 96 floats
__device__ float4 g_ealpha[NN];     // N x 4 (per-head exp(leakyrelu(alpha)))
__device__ float4 g_denom[NN];      // N x 4 softmax denominators
__device__ float  g_pooled[GG * 64];

__device__ __forceinline__ void red_add_f4(float4* addr, float4 v) {
    asm volatile("red.global.add.v4.f32 [%0], {%1,%2,%3,%4};"
                 :: "l"(addr), "f"(v.x), "f"(v.y), "f"(v.z), "f"(v.w) : "memory");
}

// ---------------- generic tiled GEMM: C[N,M] = A[N,K] @ W[K,M] + bias ----------------
// K must be a multiple of 16; M a multiple of 4. 256 threads, 64x64 tile, 4x4 per thread.
__global__ void gemm_bias_kernel(const float* __restrict__ A, const float* __restrict__ W,
                                 const float* __restrict__ bias, float* __restrict__ Cm,
                                 int Nrows, int K, int M) {
    __shared__ float As[16][65];
    __shared__ float Ws[16][65];
    int tid = threadIdx.x;
    int tx = tid & 15, ty = tid >> 4;
    int row0 = blockIdx.y * 64, col0 = blockIdx.x * 64;
    float acc[4][4];
#pragma unroll
    for (int i = 0; i < 4; i++)
#pragma unroll
        for (int j = 0; j < 4; j++) acc[i][j] = 0.f;

    for (int k0 = 0; k0 < K; k0 += 16) {
#pragma unroll
        for (int i = 0; i < 4; i++) {
            int lin = tid + i * 256;
            // A tile: coalesced 16-float rows
            int r = lin >> 4, kk = lin & 15;
            int gr = row0 + r;
            As[kk][r] = (gr < Nrows) ? A[(size_t)gr * K + k0 + kk] : 0.f;
            // W tile: coalesced 64-float rows
            int c = lin & 63, kk2 = lin >> 6;
            int gc = col0 + c;
            Ws[kk2][c] = (gc < M) ? W[(size_t)(k0 + kk2) * M + gc] : 0.f;
        }
        __syncthreads();
#pragma unroll
        for (int kk = 0; kk < 16; kk++) {
            float a[4], w[4];
#pragma unroll
            for (int i = 0; i < 4; i++) a[i] = As[kk][ty * 4 + i];
#pragma unroll
            for (int j = 0; j < 4; j++) w[j] = Ws[kk][tx * 4 + j];
#pragma unroll
            for (int i = 0; i < 4; i++)
#pragma unroll
                for (int j = 0; j < 4; j++) acc[i][j] += a[i] * w[j];
        }
        __syncthreads();
    }
    int gc = col0 + tx * 4;
    if (gc >= M) return;
    float4 bv = *(const float4*)(bias + gc);
#pragma unroll
    for (int i = 0; i < 4; i++) {
        int gr = row0 + ty * 4 + i;
        if (gr < Nrows) {
            float4 v = make_float4(acc[i][0] + bv.x, acc[i][1] + bv.y,
                                   acc[i][2] + bv.z, acc[i][3] + bv.w);
            *(float4*)(Cm + (size_t)gr * M + gc) = v;
        }
    }
}

// ---------------- per-node attention logits: ealpha[n,h] = exp(leakyrelu(sum_c xW*att)) --------
__global__ void alpha_kernel(const float* __restrict__ xW, const float* __restrict__ att,
                             float4* __restrict__ ealpha, int N, int C) {
    int gw = (blockIdx.x * blockDim.x + threadIdx.x) >> 5;
    int lane = threadIdx.x & 31;
    if (gw >= N) return;
    int h = lane >> 3, l = lane & 7;
    const float* row = xW + (size_t)gw * 4 * C + (size_t)h * C;
    const float* a = att + h * C;
    float s = 0.f;
    for (int c = l; c < C; c += 8) s += row[c] * a[c];
    s += __shfl_down_sync(0xffffffffu, s, 4);
    s += __shfl_down_sync(0xffffffffu, s, 2);
    s += __shfl_down_sync(0xffffffffu, s, 1);
    if (l == 0) {
        float v = s > 0.f ? s : 0.2f * s;   // leaky_relu(., 0.2)
        ((float*)(ealpha + gw))[h] = __expf(v);
    }
}

// ---------------- softmax denominators: denom[dst] += ealpha[src] ----------------
__global__ void edge_denom_kernel(const int* __restrict__ src, const int* __restrict__ dst,
                                  const float4* __restrict__ ealpha, float4* __restrict__ denom,
                                  int E) {
    int e = blockIdx.x * blockDim.x + threadIdx.x;
    if (e >= E) return;
    float4 v = __ldg(&ealpha[src[e]]);
    red_add_f4(&denom[dst[e]], v);
}

// ---------------- aggregate: out[dst,c] += 0.25 * sum_h w_h * xW[src,h,c]  (warp per edge) -----
__global__ void edge_agg_kernel(const int* __restrict__ src, const int* __restrict__ dst,
                                const float4* __restrict__ ealpha, const float4* __restrict__ denom,
                                const float* __restrict__ xW, float* __restrict__ outF,
                                int E, int C) {
    int gw = (blockIdx.x * blockDim.x + threadIdx.x) >> 5;
    int lane = threadIdx.x & 31;
    if (gw >= E) return;
    int s = __ldg(&src[gw]);
    int d = __ldg(&dst[gw]);
    float4 ea = __ldg(&ealpha[s]);
    float4 dn = __ldg(&denom[d]);
    float w0 = 0.25f * ea.x / (dn.x + 1e-16f);
    float w1 = 0.25f * ea.y / (dn.y + 1e-16f);
    float w2 = 0.25f * ea.z / (dn.z + 1e-16f);
    float w3 = 0.25f * ea.w / (dn.w + 1e-16f);
    int C4 = C >> 2;
    const float4* xw = (const float4*)(xW + (size_t)s * 4 * C);
    float4* o = (float4*)(outF + (size_t)d * C);
    for (int j = lane; j < C4; j += 32) {
        float4 m0 = __ldg(&xw[j]);
        float4 m1 = __ldg(&xw[C4 + j]);
        float4 m2 = __ldg(&xw[2 * C4 + j]);
        float4 m3 = __ldg(&xw[3 * C4 + j]);
        float4 acc;
        acc.x = w0 * m0.x + w1 * m1.x + w2 * m2.x + w3 * m3.x;
        acc.y = w0 * m0.y + w1 * m1.y + w2 * m2.y + w3 * m3.y;
        acc.z = w0 * m0.z + w1 * m1.z + w2 * m2.z + w3 * m3.z;
        acc.w = w0 * m0.w + w1 * m1.w + w2 * m2.w + w3 * m3.w;
        red_add_f4(&o[j], acc);
    }
}

// ---------------- global mean pool (batch is sorted => binary search per graph) -------------
__global__ void pool_kernel(const float* __restrict__ h, const int* __restrict__ batch,
                            float* __restrict__ pooled, int N) {
    int g = blockIdx.x;  // 0..63
    // lower_bound(g), lower_bound(g+1)
    int lo = 0, hi = N;
    while (lo < hi) { int mid = (lo + hi) >> 1; if (batch[mid] < g) lo = mid + 1; else hi = mid; }
    int start = lo;
    lo = start; hi = N;
    while (lo < hi) { int mid = (lo + hi) >> 1; if (batch[mid] < g + 1) lo = mid + 1; else hi = mid; }
    int end = lo;

    int t = threadIdx.x;          // 256 threads
    int c = t & 63, chunk = t >> 6;
    float acc = 0.f;
    for (int n = start + chunk; n < end; n += 4) acc += h[(size_t)n * 64 + c];
    __shared__ float sh[4][64];
    sh[chunk][c] = acc;
    __syncthreads();
    if (chunk == 0) {
        float s = sh[0][c] + sh[1][c] + sh[2][c] + sh[3][c];
        int cnt = end - start;
        pooled[g * 64 + c] = s / (float)(cnt > 0 ? cnt : 1);
    }
}

// ---------------- classifier + log_softmax ----------------
__global__ void fc_kernel(const float* __restrict__ pooled, const float* __restrict__ Wfc,
                          const float* __restrict__ bfc, float* __restrict__ out) {
    __shared__ float logits[GG][10];
    int t = threadIdx.x;  // 640 threads
    if (t < GG * 10) {
        int g = t / 10, o = t % 10;
        float s = bfc[o];
        const float* pr = pooled + g * 64;
        for (int k = 0; k < 64; k++) s += pr[k] * Wfc[k * 10 + o];
        logits[g][o] = s;
    }
    __syncthreads();
    if (t < GG) {
        float mx = -1e30f;
        for (int o = 0; o < 10; o++) mx = fmaxf(mx, logits[t][o]);
        float sum = 0.f;
        for (int o = 0; o < 10; o++) sum += __expf(logits[t][o] - mx);
        float lse = mx + __logf(sum);
        for (int o = 0; o < 10; o++) out[t * 10 + o] = logits[t][o] - lse;
    }
}

// ---------------- launcher ----------------
extern "C" void kernel_launch(void* const* d_in, const int* in_sizes, int n_in,
                              void* d_out, int out_size) {
    const float* x    = (const float*)d_in[0];
    const int*   ei   = (const int*)d_in[1];
    const int*   batch= (const int*)d_in[2];
    const float* Wm1  = (const float*)d_in[3];
    const float* bm1  = (const float*)d_in[4];
    const float* att1 = (const float*)d_in[5];
    const float* Ws1  = (const float*)d_in[6];
    const float* bs1  = (const float*)d_in[7];
    const float* Wm2  = (const float*)d_in[8];
    const float* bm2  = (const float*)d_in[9];
    const float* att2 = (const float*)d_in[10];
    const float* Wm3  = (const float*)d_in[11];
    const float* bm3  = (const float*)d_in[12];
    const float* att3 = (const float*)d_in[13];
    const float* Ws3  = (const float*)d_in[14];
    const float* bs3  = (const float*)d_in[15];
    const float* Wfc  = (const float*)d_in[16];
    const float* bfc  = (const float*)d_in[17];
    float* out = (float*)d_out;

    const int N = NN;
    const int E = in_sizes[1] / 2;
    const int* src = ei;
    const int* dst = ei + E;

    float4 *p_xW4, *p_B4, *p_C4, *p_ea, *p_dn;
    float *p_pl;
    cudaGetSymbolAddress((void**)&p_xW4, g_xW4);
    cudaGetSymbolAddress((void**)&p_B4, g_B4);
    cudaGetSymbolAddress((void**)&p_C4, g_C4);
    cudaGetSymbolAddress((void**)&p_ea, g_ealpha);
    cudaGetSymbolAddress((void**)&p_dn, g_denom);
    cudaGetSymbolAddress((void**)&p_pl, g_pooled);
    float* p_xW = (float*)p_xW4;
    float* p_B = (float*)p_B4;
    float* p_C = (float*)p_C4;

    const int rowTiles = (N + 63) / 64;               // 782
    const int alphaBlocks = (N * 32 + 255) / 256;     // warp per node
    const int eThreadBlocks = (E + 255) / 256;
    const int eWarpBlocks = (E + 7) / 8;              // warp per edge

    // ---------- Layer 1: F_IN=64 -> H1=96 ----------
    gemm_bias_kernel<<<dim3(6, rowTiles), 256>>>(x, Wm1, bm1, p_xW, N, 64, 384);
    alpha_kernel<<<alphaBlocks, 256>>>(p_xW, att1, p_ea, N, 96);
    gemm_bias_kernel<<<dim3(2, rowTiles), 256>>>(x, Ws1, bs1, p_B, N, 64, 96);   // self term
    cudaMemsetAsync(p_dn, 0, (size_t)N * sizeof(float4));
    edge_denom_kernel<<<eThreadBlocks, 256>>>(src, dst, p_ea, p_dn, E);
    edge_agg_kernel<<<eWarpBlocks, 256>>>(src, dst, p_ea, p_dn, p_xW, p_B, E, 96);

    // ---------- Layer 2: H1=96 -> H1=96 (self = identity) ----------
    gemm_bias_kernel<<<dim3(6, rowTiles), 256>>>(p_B, Wm2, bm2, p_xW, N, 96, 384);
    alpha_kernel<<<alphaBlocks, 256>>>(p_xW, att2, p_ea, N, 96);
    cudaMemcpyAsync(p_C, p_B, (size_t)N * 96 * sizeof(float), cudaMemcpyDeviceToDevice);
    cudaMemsetAsync(p_dn, 0, (size_t)N * sizeof(float4));
    edge_denom_kernel<<<eThreadBlocks, 256>>>(src, dst, p_ea, p_dn, E);
    edge_agg_kernel<<<eWarpBlocks, 256>>>(src, dst, p_ea, p_dn, p_xW, p_C, E, 96);

    // ---------- Layer 3: H1=96 -> C3=64 ----------
    gemm_bias_kernel<<<dim3(4, rowTiles), 256>>>(p_C, Wm3, bm3, p_xW, N, 96, 256);
    alpha_kernel<<<alphaBlocks, 256>>>(p_xW, att3, p_ea, N, 64);
    gemm_bias_kernel<<<dim3(1, rowTiles), 256>>>(p_C, Ws3, bs3, p_B, N, 96, 64);  // self term
    cudaMemsetAsync(p_dn, 0, (size_t)N * sizeof(float4));
    edge_denom_kernel<<<eThreadBlocks, 256>>>(src, dst, p_ea, p_dn, E);
    edge_agg_kernel<<<eWarpBlocks, 256>>>(src, dst, p_ea, p_dn, p_xW, p_B, E, 64);

    // ---------- pool + classifier ----------
    pool_kernel<<<GG, 256>>>(p_B, batch, p_pl, N);
    fc_kernel<<<1, 640>>>(p_pl, Wfc, bfc, out);
}

// round 2
// speedup vs baseline: 1.4325x; 1.4325x over previous
#include <cuda_runtime.h>
#include <math.h>

#define NN 50000
#define GG 64

// ---------------- scratch ----------------
__device__ float4 g_xW4[NN * 96];   // N x 384 floats (max 4*96)
__device__ float4 g_B4[NN * 24];    // N x 96
__device__ float4 g_C4[NN * 24];    // N x 96
__device__ float4 g_ealpha[NN];     // exp(leakyrelu(alpha)) per head
__device__ float4 g_denom[NN];
__device__ float4 g_invd[NN];
__device__ float  g_v[100 * 4];     // v[k][h] + trailing c[h] at k=K
__device__ float  g_pooled[GG * 64];

__device__ __forceinline__ void red_add_f4(float4* addr, float4 v) {
    asm volatile("red.global.add.v4.f32 [%0], {%1,%2,%3,%4};"
                 :: "l"(addr), "f"(v.x), "f"(v.y), "f"(v.z), "f"(v.w) : "memory");
}

// ---------------- GEMM: C[N,M] = A[N,K] @ W[K,M] + bias ----------------
// 128x64 tile, 256 threads, 8x4 per thread. K mult of 8, M mult of 4.
__global__ void gemm_bias128(const float* __restrict__ A, const float* __restrict__ W,
                             const float* __restrict__ bias, float* __restrict__ Cm,
                             int Nrows, int K, int M) {
    __shared__ float As[8][128];
    __shared__ float Ws[8][64];
    int tid = threadIdx.x;
    int tx = tid & 15;         // 16 col groups * 4
    int ty = tid >> 4;         // 16 row groups * 8
    int row0 = blockIdx.y * 128, col0 = blockIdx.x * 64;
    float acc[8][4];
#pragma unroll
    for (int i = 0; i < 8; i++)
#pragma unroll
        for (int j = 0; j < 4; j++) acc[i][j] = 0.f;

    int ar = tid >> 1;              // 0..127
    int akq = (tid & 1) * 4;        // 0 or 4
    int gr_load = row0 + ar;
    int wkk = tid >> 4;             // 0..7 (for tid<128)
    int wcq = (tid & 15) * 4;

    for (int k0 = 0; k0 < K; k0 += 8) {
        float4 av = (gr_load < Nrows) ? *(const float4*)(A + (size_t)gr_load * K + k0 + akq)
                                      : make_float4(0.f, 0.f, 0.f, 0.f);
        As[akq + 0][ar] = av.x; As[akq + 1][ar] = av.y;
        As[akq + 2][ar] = av.z; As[akq + 3][ar] = av.w;
        if (tid < 128) {
            int gc = col0 + wcq;
            float4 wv = (gc < M) ? *(const float4*)(W + (size_t)(k0 + wkk) * M + gc)
                                 : make_float4(0.f, 0.f, 0.f, 0.f);
            Ws[wkk][wcq + 0] = wv.x; Ws[wkk][wcq + 1] = wv.y;
            Ws[wkk][wcq + 2] = wv.z; Ws[wkk][wcq + 3] = wv.w;
        }
        __syncthreads();
#pragma unroll
        for (int kk = 0; kk < 8; kk++) {
            float a[8], w[4];
#pragma unroll
            for (int i = 0; i < 8; i++) a[i] = As[kk][ty * 8 + i];
#pragma unroll
            for (int j = 0; j < 4; j++) w[j] = Ws[kk][tx * 4 + j];
#pragma unroll
            for (int i = 0; i < 8; i++)
#pragma unroll
                for (int j = 0; j < 4; j++) acc[i][j] += a[i] * w[j];
        }
        __syncthreads();
    }
    int gc = col0 + tx * 4;
    if (gc >= M) return;
    float4 bv = *(const float4*)(bias + gc);
#pragma unroll
    for (int i = 0; i < 8; i++) {
        int gr = row0 + ty * 8 + i;
        if (gr < Nrows) {
            float4 v = make_float4(acc[i][0] + bv.x, acc[i][1] + bv.y,
                                   acc[i][2] + bv.z, acc[i][3] + bv.w);
            *(float4*)(Cm + (size_t)gr * M + gc) = v;
        }
    }
}

// ---------------- projection: v[k][h] = sum_c Wm[k, h*C+c]*att[h,c]; c[h]=bm_h.att_h ------
__global__ void proj_kernel(const float* __restrict__ Wm, const float* __restrict__ bm,
                            const float* __restrict__ att, float* __restrict__ v,
                            int K, int C) {
    int tid = threadIdx.x;
    int k = tid >> 2, h = tid & 3;
    if (k < K) {
        const float* wr = Wm + (size_t)k * 4 * C + h * C;
        const float* ar = att + h * C;
        float s = 0.f;
        for (int c = 0; c < C; c++) s += wr[c] * ar[c];
        v[k * 4 + h] = s;
    } else if (k == K) {
        const float* br = bm + h * C;
        const float* ar = att + h * C;
        float s = 0.f;
        for (int c = 0; c < C; c++) s += br[c] * ar[c];
        v[K * 4 + h] = s;
    }
}

// ---------------- ealpha[n,h] = exp(leakyrelu(x[n].v_h + c_h)) (warp per node) -----------
__global__ void alpha_kernel(const float* __restrict__ x, const float* __restrict__ v,
                             float4* __restrict__ ealpha, int N, int K) {
    int gw = (blockIdx.x * blockDim.x + threadIdx.x) >> 5;
    int lane = threadIdx.x & 31;
    if (gw >= N) return;
    const float* xr = x + (size_t)gw * K;
    float s0 = 0.f, s1 = 0.f, s2 = 0.f, s3 = 0.f;
    for (int k = lane; k < K; k += 32) {
        float xv = xr[k];
        float4 vv = *(const float4*)(v + k * 4);
        s0 += xv * vv.x; s1 += xv * vv.y; s2 += xv * vv.z; s3 += xv * vv.w;
    }
#pragma unroll
    for (int off = 16; off >= 1; off >>= 1) {
        s0 += __shfl_xor_sync(0xffffffffu, s0, off);
        s1 += __shfl_xor_sync(0xffffffffu, s1, off);
        s2 += __shfl_xor_sync(0xffffffffu, s2, off);
        s3 += __shfl_xor_sync(0xffffffffu, s3, off);
    }
    if (lane == 0) {
        float4 cv = *(const float4*)(v + K * 4);
        float a0 = s0 + cv.x, a1 = s1 + cv.y, a2 = s2 + cv.z, a3 = s3 + cv.w;
        a0 = a0 > 0.f ? a0 : 0.2f * a0;
        a1 = a1 > 0.f ? a1 : 0.2f * a1;
        a2 = a2 > 0.f ? a2 : 0.2f * a2;
        a3 = a3 > 0.f ? a3 : 0.2f * a3;
        ealpha[gw] = make_float4(__expf(a0), __expf(a1), __expf(a2), __expf(a3));
    }
}

// ---------------- denom[dst] += ealpha[src] ----------------
__global__ void edge_denom_kernel(const int* __restrict__ src, const int* __restrict__ dst,
                                  const float4* __restrict__ ealpha, float4* __restrict__ denom,
                                  int E) {
    int e = blockIdx.x * blockDim.x + threadIdx.x;
    if (e >= E) return;
    float4 v = __ldg(&ealpha[src[e]]);
    red_add_f4(&denom[dst[e]], v);
}

// ---------------- invd = 0.25/(denom+1e-16) ----------------
__global__ void inv_kernel(const float4* __restrict__ denom, float4* __restrict__ invd, int N) {
    int n = blockIdx.x * blockDim.x + threadIdx.x;
    if (n >= N) return;
    float4 d = denom[n];
    invd[n] = make_float4(0.25f / (d.x + 1e-16f), 0.25f / (d.y + 1e-16f),
                          0.25f / (d.z + 1e-16f), 0.25f / (d.w + 1e-16f));
}

// ---------------- out[dst,:] += sum_h w_h * xW[src,h,:] ----------------
// C=96: 24 lanes/edge, 1 edge/warp.  C=64: 16 lanes/edge, 2 edges/warp.
template<int C>
__global__ void edge_agg_kernel(const int* __restrict__ src, const int* __restrict__ dst,
                                const float4* __restrict__ ealpha, const float4* __restrict__ invd,
                                const float* __restrict__ xW, float* __restrict__ outF, int E) {
    constexpr int C4 = C / 4;
    constexpr int EPW = 32 / C4;
    int warp = (blockIdx.x * blockDim.x + threadIdx.x) >> 5;
    int lane = threadIdx.x & 31;
    int sub = lane / C4;
    int j = lane - sub * C4;
    if (sub >= EPW) return;
    int e = warp * EPW + sub;
    if (e >= E) return;
    int s = __ldg(&src[e]);
    int d = __ldg(&dst[e]);
    float4 ea = __ldg(&ealpha[s]);
    float4 iv = __ldg(&invd[d]);
    float w0 = ea.x * iv.x, w1 = ea.y * iv.y, w2 = ea.z * iv.z, w3 = ea.w * iv.w;
    const float4* xw = (const float4*)(xW + (size_t)s * 4 * C);
    float4 m0 = __ldg(&xw[j]);
    float4 m1 = __ldg(&xw[C4 + j]);
    float4 m2 = __ldg(&xw[2 * C4 + j]);
    float4 m3 = __ldg(&xw[3 * C4 + j]);
    float4 acc;
    acc.x = w0 * m0.x + w1 * m1.x + w2 * m2.x + w3 * m3.x;
    acc.y = w0 * m0.y + w1 * m1.y + w2 * m2.y + w3 * m3.y;
    acc.z = w0 * m0.z + w1 * m1.z + w2 * m2.z + w3 * m3.z;
    acc.w = w0 * m0.w + w1 * m1.w + w2 * m2.w + w3 * m3.w;
    red_add_f4((float4*)(outF + (size_t)d * C) + j, acc);
}

// ---------------- global mean pool ----------------
__global__ void pool_kernel(const float* __restrict__ h, const int* __restrict__ batch,
                            float* __restrict__ pooled, int N) {
    int g = blockIdx.x;
    int lo = 0, hi = N;
    while (lo < hi) { int mid = (lo + hi) >> 1; if (batch[mid] < g) lo = mid + 1; else hi = mid; }
    int start = lo;
    lo = start; hi = N;
    while (lo < hi) { int mid = (lo + hi) >> 1; if (batch[mid] < g + 1) lo = mid + 1; else hi = mid; }
    int end = lo;
    int t = threadIdx.x;
    int c = t & 63, chunk = t >> 6;
    float acc = 0.f;
    for (int n = start + chunk; n < end; n += 4) acc += h[(size_t)n * 64 + c];
    __shared__ float sh[4][64];
    sh[chunk][c] = acc;
    __syncthreads();
    if (chunk == 0) {
        float s = sh[0][c] + sh[1][c] + sh[2][c] + sh[3][c];
        int cnt = end - start;
        pooled[g * 64 + c] = s / (float)(cnt > 0 ? cnt : 1);
    }
}

// ---------------- classifier + log_softmax ----------------
__global__ void fc_kernel(const float* __restrict__ pooled, const float* __restrict__ Wfc,
                          const float* __restrict__ bfc, float* __restrict__ out) {
    __shared__ float logits[GG][10];
    int t = threadIdx.x;
    if (t < GG * 10) {
        int g = t / 10, o = t % 10;
        float s = bfc[o];
        const float* pr = pooled + g * 64;
        for (int k = 0; k < 64; k++) s += pr[k] * Wfc[k * 10 + o];
        logits[g][o] = s;
    }
    __syncthreads();
    if (t < GG) {
        float mx = -1e30f;
        for (int o = 0; o < 10; o++) mx = fmaxf(mx, logits[t][o]);
        float sum = 0.f;
        for (int o = 0; o < 10; o++) sum += __expf(logits[t][o] - mx);
        float lse = mx + __logf(sum);
        for (int o = 0; o < 10; o++) out[t * 10 + o] = logits[t][o] - lse;
    }
}

// ---------------- launcher ----------------
extern "C" void kernel_launch(void* const* d_in, const int* in_sizes, int n_in,
                              void* d_out, int out_size) {
    const float* x    = (const float*)d_in[0];
    const int*   ei   = (const int*)d_in[1];
    const int*   batch= (const int*)d_in[2];
    const float* Wm1  = (const float*)d_in[3];
    const float* bm1  = (const float*)d_in[4];
    const float* att1 = (const float*)d_in[5];
    const float* Ws1  = (const float*)d_in[6];
    const float* bs1  = (const float*)d_in[7];
    const float* Wm2  = (const float*)d_in[8];
    const float* bm2  = (const float*)d_in[9];
    const float* att2 = (const float*)d_in[10];
    const float* Wm3  = (const float*)d_in[11];
    const float* bm3  = (const float*)d_in[12];
    const float* att3 = (const float*)d_in[13];
    const float* Ws3  = (const float*)d_in[14];
    const float* bs3  = (const float*)d_in[15];
    const float* Wfc  = (const float*)d_in[16];
    const float* bfc  = (const float*)d_in[17];
    float* out = (float*)d_out;

    const int N = NN;
    const int E = in_sizes[1] / 2;
    const int* src = ei;
    const int* dst = ei + E;

    float4 *p_xW4, *p_B4, *p_C4, *p_ea, *p_dn, *p_iv;
    float *p_pl, *p_v;
    cudaGetSymbolAddress((void**)&p_xW4, g_xW4);
    cudaGetSymbolAddress((void**)&p_B4, g_B4);
    cudaGetSymbolAddress((void**)&p_C4, g_C4);
    cudaGetSymbolAddress((void**)&p_ea, g_ealpha);
    cudaGetSymbolAddress((void**)&p_dn, g_denom);
    cudaGetSymbolAddress((void**)&p_iv, g_invd);
    cudaGetSymbolAddress((void**)&p_pl, g_pooled);
    cudaGetSymbolAddress((void**)&p_v, g_v);
    float* p_xW = (float*)p_xW4;
    float* p_B = (float*)p_B4;
    float* p_C = (float*)p_C4;

    const int rowTiles = (N + 127) / 128;             // 391
    const int alphaBlocks = (N * 32 + 255) / 256;
    const int eThreadBlocks = (E + 255) / 256;
    const int nBlocks = (N + 255) / 256;
    const int agg96Blocks = (E + 7) / 8;              // 1 edge / warp
    const int agg64Blocks = (E + 15) / 16;            // 2 edges / warp

    // ---------- Layer 1: 64 -> 96 ----------
    proj_kernel<<<1, 512>>>(Wm1, bm1, att1, p_v, 64, 96);
    alpha_kernel<<<alphaBlocks, 256>>>(x, p_v, p_ea, N, 64);
    cudaMemsetAsync(p_dn, 0, (size_t)N * sizeof(float4));
    edge_denom_kernel<<<eThreadBlocks, 256>>>(src, dst, p_ea, p_dn, E);
    inv_kernel<<<nBlocks, 256>>>(p_dn, p_iv, N);
    gemm_bias128<<<dim3(6, rowTiles), 256>>>(x, Wm1, bm1, p_xW, N, 64, 384);
    gemm_bias128<<<dim3(2, rowTiles), 256>>>(x, Ws1, bs1, p_B, N, 64, 96);
    edge_agg_kernel<96><<<agg96Blocks, 256>>>(src, dst, p_ea, p_iv, p_xW, p_B, E);

    // ---------- Layer 2: 96 -> 96 (self = identity, in-place accumulate) ----------
    proj_kernel<<<1, 512>>>(Wm2, bm2, att2, p_v, 96, 96);
    alpha_kernel<<<alphaBlocks, 256>>>(p_B, p_v, p_ea, N, 96);
    cudaMemsetAsync(p_dn, 0, (size_t)N * sizeof(float4));
    edge_denom_kernel<<<eThreadBlocks, 256>>>(src, dst, p_ea, p_dn, E);
    inv_kernel<<<nBlocks, 256>>>(p_dn, p_iv, N);
    gemm_bias128<<<dim3(6, rowTiles), 256>>>(p_B, Wm2, bm2, p_xW, N, 96, 384);
    edge_agg_kernel<96><<<agg96Blocks, 256>>>(src, dst, p_ea, p_iv, p_xW, p_B, E);

    // ---------- Layer 3: 96 -> 64 ----------
    proj_kernel<<<1, 512>>>(Wm3, bm3, att3, p_v, 96, 64);
    alpha_kernel<<<alphaBlocks, 256>>>(p_B, p_v, p_ea, N, 96);
    cudaMemsetAsync(p_dn, 0, (size_t)N * sizeof(float4));
    edge_denom_kernel<<<eThreadBlocks, 256>>>(src, dst, p_ea, p_dn, E);
    inv_kernel<<<nBlocks, 256>>>(p_dn, p_iv, N);
    gemm_bias128<<<dim3(4, rowTiles), 256>>>(p_B, Wm3, bm3, p_xW, N, 96, 256);
    gemm_bias128<<<dim3(1, rowTiles), 256>>>(p_B, Ws3, bs3, p_C, N, 96, 64);
    edge_agg_kernel<64><<<agg64Blocks, 256>>>(src, dst, p_ea, p_iv, p_xW, p_C, E);

    // ---------- pool + classifier ----------
    pool_kernel<<<GG, 256>>>(p_C, batch, p_pl, N);
    fc_kernel<<<1, 640>>>(p_pl, Wfc, bfc, out);
}

// round 6
// speedup vs baseline: 1.9476x; 1.3596x over previous
#include <cuda_runtime.h>
#include <math.h>
#include <stdint.h>

#define NN 50000
#define GG 64

// ---------------- scratch ----------------
__device__ float4 g_xW4[NN * 96];   // N x 384 floats (max 4*96)
__device__ float4 g_B4[NN * 24];    // N x 96
__device__ float4 g_C4[NN * 24];    // N x 96
__device__ float4 g_ealpha[NN];
__device__ float4 g_denom[NN];
__device__ float4 g_invd[NN];
__device__ float  g_v[100 * 4];
__device__ float  g_pooled[GG * 64];

__device__ __forceinline__ void red_add_f4(float4* addr, float4 v) {
    asm volatile("red.global.add.v4.f32 [%0], {%1,%2,%3,%4};"
                 :: "l"(addr), "f"(v.x), "f"(v.y), "f"(v.z), "f"(v.w) : "memory");
}

__device__ __forceinline__ float to_tf32(float x) {
    uint32_t u;
    asm("cvt.rna.tf32.f32 %0, %1;" : "=r"(u) : "f"(x));
    return __uint_as_float(u);
}

// ---------------- TF32 tensor-core GEMM: C[N,M] = A[N,K] @ W[K,M] + bias ----------------
// Block 64(M-rows) x 128(cols), 256 threads = 8 warps (2x4), warp tile 32x32,
// K-chunk 32, mma.m16n8k8.tf32. K must be a multiple of 32, M a multiple of 4.
__global__ void gemm_tf32(const float* __restrict__ A, const float* __restrict__ W,
                          const float* __restrict__ bias, float* __restrict__ Cm,
                          int Nrows, int K, int M) {
    __shared__ float As[64][36];    // [row][k], stride 36: frag loads conflict-free
    __shared__ float Ws[32][136];   // [k][col], stride 136: frag loads conflict-free

    int tid = threadIdx.x;
    int warp = tid >> 5, lane = tid & 31;
    int g = lane >> 2, t = lane & 3;        // mma group / thread-in-group
    int warpM = warp >> 2, warpN = warp & 3;
    int rb = warpM * 32, cb = warpN * 32;
    int row0 = blockIdx.y * 64, col0 = blockIdx.x * 128;

    float c[2][4][4];
#pragma unroll
    for (int i = 0; i < 2; i++)
#pragma unroll
        for (int j = 0; j < 4; j++)
#pragma unroll
            for (int q = 0; q < 4; q++) c[i][j][q] = 0.f;

    for (int k0 = 0; k0 < K; k0 += 32) {
        // A tile: 64 rows x 32 k
#pragma unroll
        for (int i = 0; i < 2; i++) {
            int l = tid + i * 256;          // 0..511
            int r = l >> 3;
            int q = (l & 7) * 4;
            int gr = row0 + r;
            float4 av = (gr < Nrows) ? *(const float4*)(A + (size_t)gr * K + k0 + q)
                                     : make_float4(0.f, 0.f, 0.f, 0.f);
            av.x = to_tf32(av.x); av.y = to_tf32(av.y);
            av.z = to_tf32(av.z); av.w = to_tf32(av.w);
            *(float4*)(&As[r][q]) = av;
        }
        // W tile: 32 k x 128 cols
#pragma unroll
        for (int i = 0; i < 4; i++) {
            int l = tid + i * 256;          // 0..1023
            int kk = l >> 5;
            int c4 = (l & 31) * 4;
            int gc = col0 + c4;
            float4 wv = (gc < M) ? *(const float4*)(W + (size_t)(k0 + kk) * M + gc)
                                 : make_float4(0.f, 0.f, 0.f, 0.f);
            wv.x = to_tf32(wv.x); wv.y = to_tf32(wv.y);
            wv.z = to_tf32(wv.z); wv.w = to_tf32(wv.w);
            *(float4*)(&Ws[kk][c4]) = wv;
        }
        __syncthreads();

#pragma unroll
        for (int kk = 0; kk < 32; kk += 8) {
            uint32_t a[2][4];
#pragma unroll
            for (int i = 0; i < 2; i++) {
                int r = rb + i * 16 + g;
                a[i][0] = __float_as_uint(As[r][kk + t]);
                a[i][1] = __float_as_uint(As[r + 8][kk + t]);
                a[i][2] = __float_as_uint(As[r][kk + t + 4]);
                a[i][3] = __float_as_uint(As[r + 8][kk + t + 4]);
            }
            uint32_t b[4][2];
#pragma unroll
            for (int j = 0; j < 4; j++) {
                int cc = cb + j * 8 + g;
                b[j][0] = __float_as_uint(Ws[kk + t][cc]);
                b[j][1] = __float_as_uint(Ws[kk + t + 4][cc]);
            }
#pragma unroll
            for (int i = 0; i < 2; i++)
#pragma unroll
                for (int j = 0; j < 4; j++) {
                    asm volatile(
                        "mma.sync.aligned.m16n8k8.row.col.f32.tf32.tf32.f32 "
                        "{%0,%1,%2,%3}, {%4,%5,%6,%7}, {%8,%9}, {%0,%1,%2,%3};"
                        : "+f"(c[i][j][0]), "+f"(c[i][j][1]),
                          "+f"(c[i][j][2]), "+f"(c[i][j][3])
                        : "r"(a[i][0]), "r"(a[i][1]), "r"(a[i][2]), "r"(a[i][3]),
                          "r"(b[j][0]), "r"(b[j][1]));
                }
        }
        __syncthreads();
    }

    // epilogue: bias + store
#pragma unroll
    for (int j = 0; j < 4; j++) {
        int gc = col0 + cb + j * 8 + 2 * t;
        if (gc >= M) continue;
        float b0 = bias[gc], b1 = bias[gc + 1];
#pragma unroll
        for (int i = 0; i < 2; i++) {
            int gr = row0 + rb + i * 16 + g;
            if (gr < Nrows) {
                float2 v = make_float2(c[i][j][0] + b0, c[i][j][1] + b1);
                *(float2*)(Cm + (size_t)gr * M + gc) = v;
            }
            if (gr + 8 < Nrows) {
                float2 v = make_float2(c[i][j][2] + b0, c[i][j][3] + b1);
                *(float2*)(Cm + (size_t)(gr + 8) * M + gc) = v;
            }
        }
    }
}

// ---------------- projection: v[k][h] = sum_c Wm[k, h*C+c]*att[h,c]; c[h]=bm_h.att_h ------
__global__ void proj_kernel(const float* __restrict__ Wm, const float* __restrict__ bm,
                            const float* __restrict__ att, float* __restrict__ v,
                            int K, int C) {
    int tid = threadIdx.x;
    int k = tid >> 2, h = tid & 3;
    if (k < K) {
        const float* wr = Wm + (size_t)k * 4 * C + h * C;
        const float* ar = att + h * C;
        float s = 0.f;
        for (int c = 0; c < C; c++) s += wr[c] * ar[c];
        v[k * 4 + h] = s;
    } else if (k == K) {
        const float* br = bm + h * C;
        const float* ar = att + h * C;
        float s = 0.f;
        for (int c = 0; c < C; c++) s += br[c] * ar[c];
        v[K * 4 + h] = s;
    }
}

// ---------------- ealpha[n,h] = exp(leakyrelu(x[n].v_h + c_h)) (warp per node) -----------
__global__ void alpha_kernel(const float* __restrict__ x, const float* __restrict__ v,
                             float4* __restrict__ ealpha, int N, int K) {
    int gw = (blockIdx.x * blockDim.x + threadIdx.x) >> 5;
    int lane = threadIdx.x & 31;
    if (gw >= N) return;
    const float* xr = x + (size_t)gw * K;
    float s0 = 0.f, s1 = 0.f, s2 = 0.f, s3 = 0.f;
    for (int k = lane; k < K; k += 32) {
        float xv = xr[k];
        float4 vv = *(const float4*)(v + k * 4);
        s0 += xv * vv.x; s1 += xv * vv.y; s2 += xv * vv.z; s3 += xv * vv.w;
    }
#pragma unroll
    for (int off = 16; off >= 1; off >>= 1) {
        s0 += __shfl_xor_sync(0xffffffffu, s0, off);
        s1 += __shfl_xor_sync(0xffffffffu, s1, off);
        s2 += __shfl_xor_sync(0xffffffffu, s2, off);
        s3 += __shfl_xor_sync(0xffffffffu, s3, off);
    }
    if (lane == 0) {
        float4 cv = *(const float4*)(v + K * 4);
        float a0 = s0 + cv.x, a1 = s1 + cv.y, a2 = s2 + cv.z, a3 = s3 + cv.w;
        a0 = a0 > 0.f ? a0 : 0.2f * a0;
        a1 = a1 > 0.f ? a1 : 0.2f * a1;
        a2 = a2 > 0.f ? a2 : 0.2f * a2;
        a3 = a3 > 0.f ? a3 : 0.2f * a3;
        ealpha[gw] = make_float4(__expf(a0), __expf(a1), __expf(a2), __expf(a3));
    }
}

// ---------------- denom[dst] += ealpha[src] ----------------
__global__ void edge_denom_kernel(const int* __restrict__ src, const int* __restrict__ dst,
                                  const float4* __restrict__ ealpha, float4* __restrict__ denom,
                                  int E) {
    int e = blockIdx.x * blockDim.x + threadIdx.x;
    if (e >= E) return;
    float4 v = __ldg(&ealpha[src[e]]);
    red_add_f4(&denom[dst[e]], v);
}

// ---------------- invd = 0.25/(denom+1e-16) ----------------
__global__ void inv_kernel(const float4* __restrict__ denom, float4* __restrict__ invd, int N) {
    int n = blockIdx.x * blockDim.x + threadIdx.x;
    if (n >= N) return;
    float4 d = denom[n];
    invd[n] = make_float4(0.25f / (d.x + 1e-16f), 0.25f / (d.y + 1e-16f),
                          0.25f / (d.z + 1e-16f), 0.25f / (d.w + 1e-16f));
}

// ---------------- out[dst,:] += sum_h w_h * xW[src,h,:] ----------------
template<int C>
__global__ void edge_agg_kernel(const int* __restrict__ src, const int* __restrict__ dst,
                                const float4* __restrict__ ealpha, const float4* __restrict__ invd,
                                const float* __restrict__ xW, float* __restrict__ outF, int E) {
    constexpr int C4 = C / 4;
    constexpr int EPW = 32 / C4;
    int warp = (blockIdx.x * blockDim.x + threadIdx.x) >> 5;
    int lane = threadIdx.x & 31;
    int sub = lane / C4;
    int j = lane - sub * C4;
    if (sub >= EPW) return;
    int e = warp * EPW + sub;
    if (e >= E) return;
    int s = __ldg(&src[e]);
    int d = __ldg(&dst[e]);
    float4 ea = __ldg(&ealpha[s]);
    float4 iv = __ldg(&invd[d]);
    float w0 = ea.x * iv.x, w1 = ea.y * iv.y, w2 = ea.z * iv.z, w3 = ea.w * iv.w;
    const float4* xw = (const float4*)(xW + (size_t)s * 4 * C);
    float4 m0 = __ldg(&xw[j]);
    float4 m1 = __ldg(&xw[C4 + j]);
    float4 m2 = __ldg(&xw[2 * C4 + j]);
    float4 m3 = __ldg(&xw[3 * C4 + j]);
    float4 acc;
    acc.x = w0 * m0.x + w1 * m1.x + w2 * m2.x + w3 * m3.x;
    acc.y = w0 * m0.y + w1 * m1.y + w2 * m2.y + w3 * m3.y;
    acc.z = w0 * m0.z + w1 * m1.z + w2 * m2.z + w3 * m3.z;
    acc.w = w0 * m0.w + w1 * m1.w + w2 * m2.w + w3 * m3.w;
    red_add_f4((float4*)(outF + (size_t)d * C) + j, acc);
}

// ---------------- global mean pool ----------------
__global__ void pool_kernel(const float* __restrict__ h, const int* __restrict__ batch,
                            float* __restrict__ pooled, int N) {
    int g = blockIdx.x;
    int lo = 0, hi = N;
    while (lo < hi) { int mid = (lo + hi) >> 1; if (batch[mid] < g) lo = mid + 1; else hi = mid; }
    int start = lo;
    lo = start; hi = N;
    while (lo < hi) { int mid = (lo + hi) >> 1; if (batch[mid] < g + 1) lo = mid + 1; else hi = mid; }
    int end = lo;
    int t = threadIdx.x;
    int c = t & 63, chunk = t >> 6;
    float acc = 0.f;
    for (int n = start + chunk; n < end; n += 4) acc += h[(size_t)n * 64 + c];
    __shared__ float sh[4][64];
    sh[chunk][c] = acc;
    __syncthreads();
    if (chunk == 0) {
        float s = sh[0][c] + sh[1][c] + sh[2][c] + sh[3][c];
        int cnt = end - start;
        pooled[g * 64 + c] = s / (float)(cnt > 0 ? cnt : 1);
    }
}

// ---------------- classifier + log_softmax ----------------
__global__ void fc_kernel(const float* __restrict__ pooled, const float* __restrict__ Wfc,
                          const float* __restrict__ bfc, float* __restrict__ out) {
    __shared__ float logits[GG][10];
    int t = threadIdx.x;
    if (t < GG * 10) {
        int g = t / 10, o = t % 10;
        float s = bfc[o];
        const float* pr = pooled + g * 64;
        for (int k = 0; k < 64; k++) s += pr[k] * Wfc[k * 10 + o];
        logits[g][o] = s;
    }
    __syncthreads();
    if (t < GG) {
        float mx = -1e30f;
        for (int o = 0; o < 10; o++) mx = fmaxf(mx, logits[t][o]);
        float sum = 0.f;
        for (int o = 0; o < 10; o++) sum += __expf(logits[t][o] - mx);
        float lse = mx + __logf(sum);
        for (int o = 0; o < 10; o++) out[t * 10 + o] = logits[t][o] - lse;
    }
}

// ---------------- launcher ----------------
extern "C" void kernel_launch(void* const* d_in, const int* in_sizes, int n_in,
                              void* d_out, int out_size) {
    const float* x    = (const float*)d_in[0];
    const int*   ei   = (const int*)d_in[1];
    const int*   batch= (const int*)d_in[2];
    const float* Wm1  = (const float*)d_in[3];
    const float* bm1  = (const float*)d_in[4];
    const float* att1 = (const float*)d_in[5];
    const float* Ws1  = (const float*)d_in[6];
    const float* bs1  = (const float*)d_in[7];
    const float* Wm2  = (const float*)d_in[8];
    const float* bm2  = (const float*)d_in[9];
    const float* att2 = (const float*)d_in[10];
    const float* Wm3  = (const float*)d_in[11];
    const float* bm3  = (const float*)d_in[12];
    const float* att3 = (const float*)d_in[13];
    const float* Ws3  = (const float*)d_in[14];
    const float* bs3  = (const float*)d_in[15];
    const float* Wfc  = (const float*)d_in[16];
    const float* bfc  = (const float*)d_in[17];
    float* out = (float*)d_out;

    const int N = NN;
    const int E = in_sizes[1] / 2;
    const int* src = ei;
    const int* dst = ei + E;

    float4 *p_xW4, *p_B4, *p_C4, *p_ea, *p_dn, *p_iv;
    float *p_pl, *p_v;
    cudaGetSymbolAddress((void**)&p_xW4, g_xW4);
    cudaGetSymbolAddress((void**)&p_B4, g_B4);
    cudaGetSymbolAddress((void**)&p_C4, g_C4);
    cudaGetSymbolAddress((void**)&p_ea, g_ealpha);
    cudaGetSymbolAddress((void**)&p_dn, g_denom);
    cudaGetSymbolAddress((void**)&p_iv, g_invd);
    cudaGetSymbolAddress((void**)&p_pl, g_pooled);
    cudaGetSymbolAddress((void**)&p_v, g_v);
    float* p_xW = (float*)p_xW4;
    float* p_B = (float*)p_B4;
    float* p_C = (float*)p_C4;

    const int rowTiles = (N + 63) / 64;               // 782 (TF32 gemm: 64-row blocks)
    const int alphaBlocks = (N * 32 + 255) / 256;
    const int eThreadBlocks = (E + 255) / 256;
    const int nBlocks = (N + 255) / 256;
    const int agg96Blocks = (E + 7) / 8;
    const int agg64Blocks = (E + 15) / 16;

    // ---------- Layer 1: 64 -> 96 ----------
    proj_kernel<<<1, 512>>>(Wm1, bm1, att1, p_v, 64, 96);
    alpha_kernel<<<alphaBlocks, 256>>>(x, p_v, p_ea, N, 64);
    cudaMemsetAsync(p_dn, 0, (size_t)N * sizeof(float4));
    edge_denom_kernel<<<eThreadBlocks, 256>>>(src, dst, p_ea, p_dn, E);
    inv_kernel<<<nBlocks, 256>>>(p_dn, p_iv, N);
    gemm_tf32<<<dim3(3, rowTiles), 256>>>(x, Wm1, bm1, p_xW, N, 64, 384);
    gemm_tf32<<<dim3(1, rowTiles), 256>>>(x, Ws1, bs1, p_B, N, 64, 96);
    edge_agg_kernel<96><<<agg96Blocks, 256>>>(src, dst, p_ea, p_iv, p_xW, p_B, E);

    // ---------- Layer 2: 96 -> 96 (self = identity, in-place accumulate) ----------
    proj_kernel<<<1, 512>>>(Wm2, bm2, att2, p_v, 96, 96);
    alpha_kernel<<<alphaBlocks, 256>>>(p_B, p_v, p_ea, N, 96);
    cudaMemsetAsync(p_dn, 0, (size_t)N * sizeof(float4));
    edge_denom_kernel<<<eThreadBlocks, 256>>>(src, dst, p_ea, p_dn, E);
    inv_kernel<<<nBlocks, 256>>>(p_dn, p_iv, N);
    gemm_tf32<<<dim3(3, rowTiles), 256>>>(p_B, Wm2, bm2, p_xW, N, 96, 384);
    edge_agg_kernel<96><<<agg96Blocks, 256>>>(src, dst, p_ea, p_iv, p_xW, p_B, E);

    // ---------- Layer 3: 96 -> 64 ----------
    proj_kernel<<<1, 512>>>(Wm3, bm3, att3, p_v, 96, 64);
    alpha_kernel<<<alphaBlocks, 256>>>(p_B, p_v, p_ea, N, 96);
    cudaMemsetAsync(p_dn, 0, (size_t)N * sizeof(float4));
    edge_denom_kernel<<<eThreadBlocks, 256>>>(src, dst, p_ea, p_dn, E);
    inv_kernel<<<nBlocks, 256>>>(p_dn, p_iv, N);
    gemm_tf32<<<dim3(2, rowTiles), 256>>>(p_B, Wm3, bm3, p_xW, N, 96, 256);
    gemm_tf32<<<dim3(1, rowTiles), 256>>>(p_B, Ws3, bs3, p_C, N, 96, 64);
    edge_agg_kernel<64><<<agg64Blocks, 256>>>(src, dst, p_ea, p_iv, p_xW, p_C, E);

    // ---------- pool + classifier ----------
    pool_kernel<<<GG, 256>>>(p_C, batch, p_pl, N);
    fc_kernel<<<1, 640>>>(p_pl, Wfc, bfc, out);
}

// round 8
// speedup vs baseline: 2.1789x; 1.1187x over previous
#include <cuda_runtime.h>
#include <cuda_fp16.h>
#include <math.h>
#include <stdint.h>

#define NN 50000
#define EE 400000
#define GG 64

// ---------------- scratch ----------------
__device__ uint16_t g_xWh[NN * 384];   // half messages, layout [n][c][h] interleaved
__device__ float4   g_B4[NN * 24];     // N x 96 features
__device__ float4   g_C4[NN * 24];     // N x 96 / N x 64
__device__ float4   g_ealpha[NN];
__device__ float    g_v[100 * 4];
__device__ float    g_pooled[GG * 64];
__device__ float    g_Wp[96 * 384];    // permuted weight
__device__ float    g_bp[384];         // permuted bias
__device__ int      g_deg[NN];
__device__ int      g_rowptr[NN + 1];
__device__ int      g_wrk[NN];
__device__ int      g_colsrc[EE];
__device__ int      g_partials[128];

__device__ __forceinline__ float to_tf32(float x) {
    uint32_t u;
    asm("cvt.rna.tf32.f32 %0, %1;" : "=r"(u) : "f"(x));
    return __uint_as_float(u);
}

// ---------------- TF32 GEMM: C[N,M] = A[N,K] @ W[K,M] + bias; OutT = float or half ------
// Block 64x128, 256 threads, warp tile 32x32, mma.m16n8k8.tf32. K%32==0, M%4==0.
template<typename OutT>
__global__ void gemm_tf32(const float* __restrict__ A, const float* __restrict__ W,
                          const float* __restrict__ bias, OutT* __restrict__ Cm,
                          int Nrows, int K, int M) {
    __shared__ float As[64][36];
    __shared__ float Ws[32][136];

    int tid = threadIdx.x;
    int warp = tid >> 5, lane = tid & 31;
    int g = lane >> 2, t = lane & 3;
    int warpM = warp >> 2, warpN = warp & 3;
    int rb = warpM * 32, cb = warpN * 32;
    int row0 = blockIdx.y * 64, col0 = blockIdx.x * 128;

    float c[2][4][4];
#pragma unroll
    for (int i = 0; i < 2; i++)
#pragma unroll
        for (int j = 0; j < 4; j++)
#pragma unroll
            for (int q = 0; q < 4; q++) c[i][j][q] = 0.f;

    for (int k0 = 0; k0 < K; k0 += 32) {
#pragma unroll
        for (int i = 0; i < 2; i++) {
            int l = tid + i * 256;
            int r = l >> 3;
            int q = (l & 7) * 4;
            int gr = row0 + r;
            float4 av = (gr < Nrows) ? *(const float4*)(A + (size_t)gr * K + k0 + q)
                                     : make_float4(0.f, 0.f, 0.f, 0.f);
            av.x = to_tf32(av.x); av.y = to_tf32(av.y);
            av.z = to_tf32(av.z); av.w = to_tf32(av.w);
            *(float4*)(&As[r][q]) = av;
        }
#pragma unroll
        for (int i = 0; i < 4; i++) {
            int l = tid + i * 256;
            int kk = l >> 5;
            int c4 = (l & 31) * 4;
            int gc = col0 + c4;
            float4 wv = (gc < M) ? *(const float4*)(W + (size_t)(k0 + kk) * M + gc)
                                 : make_float4(0.f, 0.f, 0.f, 0.f);
            wv.x = to_tf32(wv.x); wv.y = to_tf32(wv.y);
            wv.z = to_tf32(wv.z); wv.w = to_tf32(wv.w);
            *(float4*)(&Ws[kk][c4]) = wv;
        }
        __syncthreads();

#pragma unroll
        for (int kk = 0; kk < 32; kk += 8) {
            uint32_t a[2][4];
#pragma unroll
            for (int i = 0; i < 2; i++) {
                int r = rb + i * 16 + g;
                a[i][0] = __float_as_uint(As[r][kk + t]);
                a[i][1] = __float_as_uint(As[r + 8][kk + t]);
                a[i][2] = __float_as_uint(As[r][kk + t + 4]);
                a[i][3] = __float_as_uint(As[r + 8][kk + t + 4]);
            }
            uint32_t b[4][2];
#pragma unroll
            for (int j = 0; j < 4; j++) {
                int cc = cb + j * 8 + g;
                b[j][0] = __float_as_uint(Ws[kk + t][cc]);
                b[j][1] = __float_as_uint(Ws[kk + t + 4][cc]);
            }
#pragma unroll
            for (int i = 0; i < 2; i++)
#pragma unroll
                for (int j = 0; j < 4; j++) {
                    asm volatile(
                        "mma.sync.aligned.m16n8k8.row.col.f32.tf32.tf32.f32 "
                        "{%0,%1,%2,%3}, {%4,%5,%6,%7}, {%8,%9}, {%0,%1,%2,%3};"
                        : "+f"(c[i][j][0]), "+f"(c[i][j][1]),
                          "+f"(c[i][j][2]), "+f"(c[i][j][3])
                        : "r"(a[i][0]), "r"(a[i][1]), "r"(a[i][2]), "r"(a[i][3]),
                          "r"(b[j][0]), "r"(b[j][1]));
                }
        }
        __syncthreads();
    }

    constexpr bool HALF_OUT = (sizeof(OutT) == 2);
#pragma unroll
    for (int j = 0; j < 4; j++) {
        int gc = col0 + cb + j * 8 + 2 * t;
        if (gc >= M) continue;
        float b0 = bias[gc], b1 = bias[gc + 1];
#pragma unroll
        for (int i = 0; i < 2; i++) {
            int gr = row0 + rb + i * 16 + g;
            if (gr < Nrows) {
                if (HALF_OUT) {
                    __half2 hv = __floats2half2_rn(c[i][j][0] + b0, c[i][j][1] + b1);
                    *(__half2*)((uint16_t*)Cm + (size_t)gr * M + gc) = hv;
                } else {
                    *(float2*)((float*)Cm + (size_t)gr * M + gc) =
                        make_float2(c[i][j][0] + b0, c[i][j][1] + b1);
                }
            }
            if (gr + 8 < Nrows) {
                if (HALF_OUT) {
                    __half2 hv = __floats2half2_rn(c[i][j][2] + b0, c[i][j][3] + b1);
                    *(__half2*)((uint16_t*)Cm + (size_t)(gr + 8) * M + gc) = hv;
                } else {
                    *(float2*)((float*)Cm + (size_t)(gr + 8) * M + gc) =
                        make_float2(c[i][j][2] + b0, c[i][j][3] + b1);
                }
            }
        }
    }
}

// ---------------- permute W columns: Wp[k][c*4+h] = Wm[k][h*C+c]; same for bias ---------
__global__ void permw_kernel(const float* __restrict__ Wm, const float* __restrict__ bm,
                             float* __restrict__ Wp, float* __restrict__ bp, int K, int C) {
    int idx = blockIdx.x * 256 + threadIdx.x;
    int M = 4 * C;
    if (idx < K * M) {
        int k = idx / M, p = idx - k * M;
        Wp[idx] = Wm[(size_t)k * M + (p & 3) * C + (p >> 2)];
    }
    if (idx < M) bp[idx] = bm[(idx & 3) * C + (idx >> 2)];
}

// ---------------- projection: v[k][h] = sum_c Wm[k, h*C+c]*att[h,c]; c[h]=bm_h.att_h ----
__global__ void proj_kernel(const float* __restrict__ Wm, const float* __restrict__ bm,
                            const float* __restrict__ att, float* __restrict__ v,
                            int K, int C) {
    int tid = threadIdx.x;
    int k = tid >> 2, h = tid & 3;
    if (k < K) {
        const float* wr = Wm + (size_t)k * 4 * C + h * C;
        const float* ar = att + h * C;
        float s = 0.f;
        for (int c = 0; c < C; c++) s += wr[c] * ar[c];
        v[k * 4 + h] = s;
    } else if (k == K) {
        const float* br = bm + h * C;
        const float* ar = att + h * C;
        float s = 0.f;
        for (int c = 0; c < C; c++) s += br[c] * ar[c];
        v[K * 4 + h] = s;
    }
}

// ---------------- ealpha[n,h] = exp(leakyrelu(x[n].v_h + c_h)) ----------------
__global__ void alpha_kernel(const float* __restrict__ x, const float* __restrict__ v,
                             float4* __restrict__ ealpha, int N, int K) {
    int gw = (blockIdx.x * blockDim.x + threadIdx.x) >> 5;
    int lane = threadIdx.x & 31;
    if (gw >= N) return;
    const float* xr = x + (size_t)gw * K;
    float s0 = 0.f, s1 = 0.f, s2 = 0.f, s3 = 0.f;
    for (int k = lane; k < K; k += 32) {
        float xv = xr[k];
        float4 vv = *(const float4*)(v + k * 4);
        s0 += xv * vv.x; s1 += xv * vv.y; s2 += xv * vv.z; s3 += xv * vv.w;
    }
#pragma unroll
    for (int off = 16; off >= 1; off >>= 1) {
        s0 += __shfl_xor_sync(0xffffffffu, s0, off);
        s1 += __shfl_xor_sync(0xffffffffu, s1, off);
        s2 += __shfl_xor_sync(0xffffffffu, s2, off);
        s3 += __shfl_xor_sync(0xffffffffu, s3, off);
    }
    if (lane == 0) {
        float4 cv = *(const float4*)(v + K * 4);
        float a0 = s0 + cv.x, a1 = s1 + cv.y, a2 = s2 + cv.z, a3 = s3 + cv.w;
        a0 = a0 > 0.f ? a0 : 0.2f * a0;
        a1 = a1 > 0.f ? a1 : 0.2f * a1;
        a2 = a2 > 0.f ? a2 : 0.2f * a2;
        a3 = a3 > 0.f ? a3 : 0.2f * a3;
        ealpha[gw] = make_float4(__expf(a0), __expf(a1), __expf(a2), __expf(a3));
    }
}

// ---------------- CSR build ----------------
__global__ void count_kernel(const int* __restrict__ dst, int* __restrict__ deg, int E) {
    int e = blockIdx.x * blockDim.x + threadIdx.x;
    if (e < E) atomicAdd(&deg[dst[e]], 1);
}
__global__ void scan1_kernel(const int* __restrict__ deg, int* __restrict__ rp,
                             int* __restrict__ partials, int N) {
    __shared__ int s[512];
    int tid = threadIdx.x;
    int i = blockIdx.x * 512 + tid;
    int v = (i < N) ? deg[i] : 0;
    s[tid] = v;
    __syncthreads();
#pragma unroll
    for (int off = 1; off < 512; off <<= 1) {
        int t = (tid >= off) ? s[tid - off] : 0;
        __syncthreads();
        s[tid] += t;
        __syncthreads();
    }
    if (i < N) rp[i] = s[tid] - v;      // exclusive within block
    if (tid == 511) partials[blockIdx.x] = s[511];
}
__global__ void scan2_kernel(int* __restrict__ partials, int nb) {
    if (threadIdx.x == 0) {
        int run = 0;
        for (int b = 0; b < nb; b++) { int t = partials[b]; partials[b] = run; run += t; }
    }
}
__global__ void scan3_kernel(int* __restrict__ rp, int* __restrict__ wrk,
                             const int* __restrict__ partials, int N, int E) {
    int i = blockIdx.x * 512 + threadIdx.x;
    if (i < N) {
        int v = rp[i] + partials[blockIdx.x];
        rp[i] = v;
        wrk[i] = v;
    }
    if (i == 0) rp[N] = E;
}
__global__ void scatter_kernel(const int* __restrict__ src, const int* __restrict__ dst,
                               int* __restrict__ wrk, int* __restrict__ colsrc, int E) {
    int e = blockIdx.x * blockDim.x + threadIdx.x;
    if (e >= E) return;
    int pos = atomicAdd(&wrk[dst[e]], 1);
    colsrc[pos] = src[e];
}

// ---------------- CSR aggregate: warp per dst, softmax + head-mean fused -----------------
// xWh layout: [n][c][h] halves; lane handles channels lane, lane+32, (lane+64).
template<int C>
__global__ void csr_agg_kernel(const int* __restrict__ rp, const int* __restrict__ cs,
                               const float4* __restrict__ ealpha,
                               const uint16_t* __restrict__ xWh,
                               float* __restrict__ outF, int N) {
    constexpr int CPL = C / 32;
    int w = (blockIdx.x * blockDim.x + threadIdx.x) >> 5;
    int lane = threadIdx.x & 31;
    if (w >= N) return;
    int start = __ldg(&rp[w]);
    int end = __ldg(&rp[w + 1]);

    float num[CPL][4];
#pragma unroll
    for (int cc = 0; cc < CPL; cc++)
#pragma unroll
        for (int h = 0; h < 4; h++) num[cc][h] = 0.f;
    float d0 = 0.f, d1 = 0.f, d2 = 0.f, d3 = 0.f;

    for (int i = start; i < end; i++) {
        int s = __ldg(&cs[i]);
        float4 ea = __ldg(&ealpha[s]);
        d0 += ea.x; d1 += ea.y; d2 += ea.z; d3 += ea.w;
        const uint2* m = (const uint2*)(xWh + (size_t)s * C * 4);
#pragma unroll
        for (int cc = 0; cc < CPL; cc++) {
            uint2 v = __ldg(&m[lane + cc * 32]);
            __half2 p0 = *(__half2*)&v.x;
            __half2 p1 = *(__half2*)&v.y;
            float2 f0 = __half22float2(p0);
            float2 f1 = __half22float2(p1);
            num[cc][0] += ea.x * f0.x;
            num[cc][1] += ea.y * f0.y;
            num[cc][2] += ea.z * f1.x;
            num[cc][3] += ea.w * f1.y;
        }
    }
    float i0 = 0.25f / (d0 + 1e-16f);
    float i1 = 0.25f / (d1 + 1e-16f);
    float i2 = 0.25f / (d2 + 1e-16f);
    float i3 = 0.25f / (d3 + 1e-16f);
#pragma unroll
    for (int cc = 0; cc < CPL; cc++) {
        int c = lane + cc * 32;
        float* o = outF + (size_t)w * C + c;
        *o = *o + num[cc][0] * i0 + num[cc][1] * i1 + num[cc][2] * i2 + num[cc][3] * i3;
    }
}

// ---------------- global mean pool ----------------
__global__ void pool_kernel(const float* __restrict__ h, const int* __restrict__ batch,
                            float* __restrict__ pooled, int N) {
    int g = blockIdx.x;
    int lo = 0, hi = N;
    while (lo < hi) { int mid = (lo + hi) >> 1; if (batch[mid] < g) lo = mid + 1; else hi = mid; }
    int start = lo;
    lo = start; hi = N;
    while (lo < hi) { int mid = (lo + hi) >> 1; if (batch[mid] < g + 1) lo = mid + 1; else hi = mid; }
    int end = lo;
    int t = threadIdx.x;
    int c = t & 63, chunk = t >> 6;
    float acc = 0.f;
    for (int n = start + chunk; n < end; n += 4) acc += h[(size_t)n * 64 + c];
    __shared__ float sh[4][64];
    sh[chunk][c] = acc;
    __syncthreads();
    if (chunk == 0) {
        float s = sh[0][c] + sh[1][c] + sh[2][c] + sh[3][c];
        int cnt = end - start;
        pooled[g * 64 + c] = s / (float)(cnt > 0 ? cnt : 1);
    }
}

// ---------------- classifier + log_softmax ----------------
__global__ void fc_kernel(const float* __restrict__ pooled, const float* __restrict__ Wfc,
                          const float* __restrict__ bfc, float* __restrict__ out) {
    __shared__ float logits[GG][10];
    int t = threadIdx.x;
    if (t < GG * 10) {
        int g = t / 10, o = t % 10;
        float s = bfc[o];
        const float* pr = pooled + g * 64;
        for (int k = 0; k < 64; k++) s += pr[k] * Wfc[k * 10 + o];
        logits[g][o] = s;
    }
    __syncthreads();
    if (t < GG) {
        float mx = -1e30f;
        for (int o = 0; o < 10; o++) mx = fmaxf(mx, logits[t][o]);
        float sum = 0.f;
        for (int o = 0; o < 10; o++) sum += __expf(logits[t][o] - mx);
        float lse = mx + __logf(sum);
        for (int o = 0; o < 10; o++) out[t * 10 + o] = logits[t][o] - lse;
    }
}

// ---------------- launcher ----------------
extern "C" void kernel_launch(void* const* d_in, const int* in_sizes, int n_in,
                              void* d_out, int out_size) {
    const float* x    = (const float*)d_in[0];
    const int*   ei   = (const int*)d_in[1];
    const int*   batch= (const int*)d_in[2];
    const float* Wm1  = (const float*)d_in[3];
    const float* bm1  = (const float*)d_in[4];
    const float* att1 = (const float*)d_in[5];
    const float* Ws1  = (const float*)d_in[6];
    const float* bs1  = (const float*)d_in[7];
    const float* Wm2  = (const float*)d_in[8];
    const float* bm2  = (const float*)d_in[9];
    const float* att2 = (const float*)d_in[10];
    const float* Wm3  = (const float*)d_in[11];
    const float* bm3  = (const float*)d_in[12];
    const float* att3 = (const float*)d_in[13];
    const float* Ws3  = (const float*)d_in[14];
    const float* bs3  = (const float*)d_in[15];
    const float* Wfc  = (const float*)d_in[16];
    const float* bfc  = (const float*)d_in[17];
    float* out = (float*)d_out;

    const int N = NN;
    const int E = in_sizes[1] / 2;
    const int* src = ei;
    const int* dst = ei + E;

    uint16_t* p_xWh; float4 *p_B4, *p_C4, *p_ea;
    float *p_pl, *p_v, *p_Wp, *p_bp;
    int *p_deg, *p_rp, *p_wrk, *p_cs, *p_part;
    cudaGetSymbolAddress((void**)&p_xWh, g_xWh);
    cudaGetSymbolAddress((void**)&p_B4, g_B4);
    cudaGetSymbolAddress((void**)&p_C4, g_C4);
    cudaGetSymbolAddress((void**)&p_ea, g_ealpha);
    cudaGetSymbolAddress((void**)&p_pl, g_pooled);
    cudaGetSymbolAddress((void**)&p_v, g_v);
    cudaGetSymbolAddress((void**)&p_Wp, g_Wp);
    cudaGetSymbolAddress((void**)&p_bp, g_bp);
    cudaGetSymbolAddress((void**)&p_deg, g_deg);
    cudaGetSymbolAddress((void**)&p_rp, g_rowptr);
    cudaGetSymbolAddress((void**)&p_wrk, g_wrk);
    cudaGetSymbolAddress((void**)&p_cs, g_colsrc);
    cudaGetSymbolAddress((void**)&p_part, g_partials);
    float* p_B = (float*)p_B4;
    float* p_C = (float*)p_C4;

    const int rowTiles = (N + 63) / 64;
    const int alphaBlocks = (N * 32 + 255) / 256;
    const int eBlocks = (E + 255) / 256;
    const int scanBlocks = (N + 511) / 512;
    const int aggBlocks = (N * 32 + 255) / 256;   // warp per node

    // ---------- CSR build (graph shared across all 3 layers) ----------
    cudaMemsetAsync(p_deg, 0, N * sizeof(int));
    count_kernel<<<eBlocks, 256>>>(dst, p_deg, E);
    scan1_kernel<<<scanBlocks, 512>>>(p_deg, p_rp, p_part, N);
    scan2_kernel<<<1, 32>>>(p_part, scanBlocks);
    scan3_kernel<<<scanBlocks, 512>>>(p_rp, p_wrk, p_part, N, E);
    scatter_kernel<<<eBlocks, 256>>>(src, dst, p_wrk, p_cs, E);

    // ---------- Layer 1: 64 -> 96 ----------
    proj_kernel<<<1, 512>>>(Wm1, bm1, att1, p_v, 64, 96);
    alpha_kernel<<<alphaBlocks, 256>>>(x, p_v, p_ea, N, 64);
    permw_kernel<<<(64 * 384 + 255) / 256, 256>>>(Wm1, bm1, p_Wp, p_bp, 64, 96);
    gemm_tf32<uint16_t><<<dim3(3, rowTiles), 256>>>(x, p_Wp, p_bp, p_xWh, N, 64, 384);
    gemm_tf32<float><<<dim3(1, rowTiles), 256>>>(x, Ws1, bs1, p_B, N, 64, 96);
    csr_agg_kernel<96><<<aggBlocks, 256>>>(p_rp, p_cs, p_ea, p_xWh, p_B, N);

    // ---------- Layer 2: 96 -> 96 (self = identity, in-place) ----------
    proj_kernel<<<1, 512>>>(Wm2, bm2, att2, p_v, 96, 96);
    alpha_kernel<<<alphaBlocks, 256>>>(p_B, p_v, p_ea, N, 96);
    permw_kernel<<<(96 * 384 + 255) / 256, 256>>>(Wm2, bm2, p_Wp, p_bp, 96, 96);
    gemm_tf32<uint16_t><<<dim3(3, rowTiles), 256>>>(p_B, p_Wp, p_bp, p_xWh, N, 96, 384);
    csr_agg_kernel<96><<<aggBlocks, 256>>>(p_rp, p_cs, p_ea, p_xWh, p_B, N);

    // ---------- Layer 3: 96 -> 64 ----------
    proj_kernel<<<1, 512>>>(Wm3, bm3, att3, p_v, 96, 64);
    alpha_kernel<<<alphaBlocks, 256>>>(p_B, p_v, p_ea, N, 96);
    permw_kernel<<<(96 * 256 + 255) / 256, 256>>>(Wm3, bm3, p_Wp, p_bp, 96, 64);
    gemm_tf32<uint16_t><<<dim3(2, rowTiles), 256>>>(p_B, p_Wp, p_bp, p_xWh, N, 96, 256);
    gemm_tf32<float><<<dim3(1, rowTiles), 256>>>(p_B, Ws3, bs3, p_C, N, 96, 64);
    csr_agg_kernel<64><<<aggBlocks, 256>>>(p_rp, p_cs, p_ea, p_xWh, p_C, N);

    // ---------- pool + classifier ----------
    pool_kernel<<<GG, 256>>>(p_C, batch, p_pl, N);
    fc_kernel<<<1, 640>>>(p_pl, Wfc, bfc, out);
}

// round 11
// speedup vs baseline: 2.3937x; 1.0986x over previous
#include <cuda_runtime.h>
#include <cuda_fp16.h>
#include <math.h>
#include <stdint.h>

#define NN 50000
#define EE 400000
#define GG 64

// ---------------- scratch ----------------
__device__ uint16_t g_xWh[NN * 384];   // half messages, layout [n][c][h] interleaved
__device__ float4   g_B4[NN * 24];     // N x 96 features
__device__ float4   g_C4[NN * 24];     // N x 96 / N x 64
__device__ float4   g_ealpha[NN];
__device__ float    g_v[100 * 4];
__device__ float    g_pooled[GG * 64];
__device__ float    g_Wp[96 * 384];    // permuted weight
__device__ float    g_bp[384];         // permuted bias
__device__ int      g_deg[NN];
__device__ int      g_rowptr[NN + 1];
__device__ int      g_wrk[NN];
__device__ int      g_colsrc[EE];
__device__ int      g_partials[128];

__device__ __forceinline__ float to_tf32(float x) {
    uint32_t u;
    asm("cvt.rna.tf32.f32 %0, %1;" : "=r"(u) : "f"(x));
    return __uint_as_float(u);
}

// ---------------- TF32 GEMM v2: whole K in smem, 128x128 tile, one sync ----------------
// C[N,M] = A[N,K] @ W[K,M] + bias. K in {64,96} (<=96, mult of 8), M mult of 4.
// 256 threads = 8 warps (2x4), warp tile 64x32, mma.m16n8k8.tf32.
// Dynamic smem: As[128][100] + Ws[96][136] = 103424 B (2 blocks/SM on 228KB).
#define GEMM_SMEM ((128 * 100 + 96 * 136) * 4)

template<typename OutT>
__global__ void __launch_bounds__(256)
gemm_tf32_v2(const float* __restrict__ A, const float* __restrict__ W,
             const float* __restrict__ bias, OutT* __restrict__ Cm,
             int Nrows, int K, int M) {
    extern __shared__ float smem[];
    float (*As)[100] = reinterpret_cast<float(*)[100]>(smem);
    float (*Ws)[136] = reinterpret_cast<float(*)[136]>(smem + 128 * 100);

    int tid = threadIdx.x;
    int warp = tid >> 5, lane = tid & 31;
    int g = lane >> 2, t = lane & 3;
    int warpM = warp >> 2, warpN = warp & 3;
    int rb = warpM * 64, cb = warpN * 32;
    int row0 = blockIdx.y * 128, col0 = blockIdx.x * 128;

    // load A tile: 128 rows x K (float4 quanta)
    int KA4 = K >> 2;
    for (int l = tid; l < 128 * KA4; l += 256) {
        int r = l / KA4;
        int q = (l - r * KA4) * 4;
        int gr = row0 + r;
        float4 av = (gr < Nrows) ? *(const float4*)(A + (size_t)gr * K + q)
                                 : make_float4(0.f, 0.f, 0.f, 0.f);
        av.x = to_tf32(av.x); av.y = to_tf32(av.y);
        av.z = to_tf32(av.z); av.w = to_tf32(av.w);
        *(float4*)(&As[r][q]) = av;
    }
    // load W tile: K x 128
    for (int l = tid; l < K * 32; l += 256) {
        int kk = l >> 5;
        int c4 = (l & 31) * 4;
        int gc = col0 + c4;
        float4 wv = (gc < M) ? *(const float4*)(W + (size_t)kk * M + gc)
                             : make_float4(0.f, 0.f, 0.f, 0.f);
        wv.x = to_tf32(wv.x); wv.y = to_tf32(wv.y);
        wv.z = to_tf32(wv.z); wv.w = to_tf32(wv.w);
        *(float4*)(&Ws[kk][c4]) = wv;
    }
    __syncthreads();

    float c[4][4][4];
#pragma unroll
    for (int i = 0; i < 4; i++)
#pragma unroll
        for (int j = 0; j < 4; j++)
#pragma unroll
            for (int q = 0; q < 4; q++) c[i][j][q] = 0.f;

    for (int kk = 0; kk < K; kk += 8) {
        uint32_t a[4][4];
#pragma unroll
        for (int i = 0; i < 4; i++) {
            int r = rb + i * 16 + g;
            a[i][0] = __float_as_uint(As[r][kk + t]);
            a[i][1] = __float_as_uint(As[r + 8][kk + t]);
            a[i][2] = __float_as_uint(As[r][kk + t + 4]);
            a[i][3] = __float_as_uint(As[r + 8][kk + t + 4]);
        }
        uint32_t b[4][2];
#pragma unroll
        for (int j = 0; j < 4; j++) {
            int cc = cb + j * 8 + g;
            b[j][0] = __float_as_uint(Ws[kk + t][cc]);
            b[j][1] = __float_as_uint(Ws[kk + t + 4][cc]);
        }
#pragma unroll
        for (int i = 0; i < 4; i++)
#pragma unroll
            for (int j = 0; j < 4; j++) {
                asm volatile(
                    "mma.sync.aligned.m16n8k8.row.col.f32.tf32.tf32.f32 "
                    "{%0,%1,%2,%3}, {%4,%5,%6,%7}, {%8,%9}, {%0,%1,%2,%3};"
                    : "+f"(c[i][j][0]), "+f"(c[i][j][1]),
                      "+f"(c[i][j][2]), "+f"(c[i][j][3])
                    : "r"(a[i][0]), "r"(a[i][1]), "r"(a[i][2]), "r"(a[i][3]),
                      "r"(b[j][0]), "r"(b[j][1]));
            }
    }

    constexpr bool HALF_OUT = (sizeof(OutT) == 2);
#pragma unroll
    for (int j = 0; j < 4; j++) {
        int gc = col0 + cb + j * 8 + 2 * t;
        if (gc >= M) continue;
        float b0 = bias[gc], b1 = bias[gc + 1];
#pragma unroll
        for (int i = 0; i < 4; i++) {
            int gr = row0 + rb + i * 16 + g;
            if (gr < Nrows) {
                if (HALF_OUT) {
                    __half2 hv = __floats2half2_rn(c[i][j][0] + b0, c[i][j][1] + b1);
                    *(__half2*)((uint16_t*)Cm + (size_t)gr * M + gc) = hv;
                } else {
                    *(float2*)((float*)Cm + (size_t)gr * M + gc) =
                        make_float2(c[i][j][0] + b0, c[i][j][1] + b1);
                }
            }
            if (gr + 8 < Nrows) {
                if (HALF_OUT) {
                    __half2 hv = __floats2half2_rn(c[i][j][2] + b0, c[i][j][3] + b1);
                    *(__half2*)((uint16_t*)Cm + (size_t)(gr + 8) * M + gc) = hv;
                } else {
                    *(float2*)((float*)Cm + (size_t)(gr + 8) * M + gc) =
                        make_float2(c[i][j][2] + b0, c[i][j][3] + b1);
                }
            }
        }
    }
}

// ------- fused: permute W columns (Wp[k][c*4+h] = Wm[k][h*C+c], bias likewise) + proj v -------
__global__ void permw_proj_kernel(const float* __restrict__ Wm, const float* __restrict__ bm,
                                  const float* __restrict__ att,
                                  float* __restrict__ Wp, float* __restrict__ bp,
                                  float* __restrict__ v, int K, int C) {
    int idx = blockIdx.x * 256 + threadIdx.x;
    int M = 4 * C;
    if (idx < K * M) {
        int k = idx / M, p = idx - k * M;
        Wp[idx] = Wm[(size_t)k * M + (p & 3) * C + (p >> 2)];
    }
    if (idx < M) bp[idx] = bm[(idx & 3) * C + (idx >> 2)];
    if (idx < (K + 1) * 4) {
        int k = idx >> 2, h = idx & 3;
        const float* base = (k < K) ? (Wm + (size_t)k * M + h * C) : (bm + h * C);
        const float* ar = att + h * C;
        float s = 0.f;
        for (int c = 0; c < C; c++) s += base[c] * ar[c];
        v[idx] = s;
    }
}

// ---------------- ealpha[n,h] = exp(leakyrelu(x[n].v_h + c_h)) ----------------
__global__ void alpha_kernel(const float* __restrict__ x, const float* __restrict__ v,
                             float4* __restrict__ ealpha, int N, int K) {
    int gw = (blockIdx.x * blockDim.x + threadIdx.x) >> 5;
    int lane = threadIdx.x & 31;
    if (gw >= N) return;
    const float* xr = x + (size_t)gw * K;
    float s0 = 0.f, s1 = 0.f, s2 = 0.f, s3 = 0.f;
    for (int k = lane; k < K; k += 32) {
        float xv = xr[k];
        float4 vv = *(const float4*)(v + k * 4);
        s0 += xv * vv.x; s1 += xv * vv.y; s2 += xv * vv.z; s3 += xv * vv.w;
    }
#pragma unroll
    for (int off = 16; off >= 1; off >>= 1) {
        s0 += __shfl_xor_sync(0xffffffffu, s0, off);
        s1 += __shfl_xor_sync(0xffffffffu, s1, off);
        s2 += __shfl_xor_sync(0xffffffffu, s2, off);
        s3 += __shfl_xor_sync(0xffffffffu, s3, off);
    }
    if (lane == 0) {
        float4 cv = *(const float4*)(v + K * 4);
        float a0 = s0 + cv.x, a1 = s1 + cv.y, a2 = s2 + cv.z, a3 = s3 + cv.w;
        a0 = a0 > 0.f ? a0 : 0.2f * a0;
        a1 = a1 > 0.f ? a1 : 0.2f * a1;
        a2 = a2 > 0.f ? a2 : 0.2f * a2;
        a3 = a3 > 0.f ? a3 : 0.2f * a3;
        ealpha[gw] = make_float4(__expf(a0), __expf(a1), __expf(a2), __expf(a3));
    }
}

// ---------------- CSR build ----------------
__global__ void count_kernel(const int* __restrict__ dst, int* __restrict__ deg, int E) {
    int e = blockIdx.x * blockDim.x + threadIdx.x;
    if (e < E) atomicAdd(&deg[dst[e]], 1);
}
__global__ void scan1_kernel(const int* __restrict__ deg, int* __restrict__ rp,
                             int* __restrict__ partials, int N) {
    __shared__ int s[512];
    int tid = threadIdx.x;
    int i = blockIdx.x * 512 + tid;
    int v = (i < N) ? deg[i] : 0;
    s[tid] = v;
    __syncthreads();
#pragma unroll
    for (int off = 1; off < 512; off <<= 1) {
        int t = (tid >= off) ? s[tid - off] : 0;
        __syncthreads();
        s[tid] += t;
        __syncthreads();
    }
    if (i < N) rp[i] = s[tid] - v;
    if (tid == 511) partials[blockIdx.x] = s[511];
}
// adds prefix of partials (computed per-block) and writes rowptr + work copy
__global__ void scan_fix_kernel(int* __restrict__ rp, int* __restrict__ wrk,
                                const int* __restrict__ partials, int N, int E) {
    int b = blockIdx.x;
    int base = 0;
    for (int i = 0; i < b; i++) base += partials[i];
    int i = b * 512 + threadIdx.x;
    if (i < N) {
        int v = rp[i] + base;
        rp[i] = v;
        wrk[i] = v;
    }
    if (b == 0 && threadIdx.x == 0) rp[N] = E;
}
__global__ void scatter_kernel(const int* __restrict__ src, const int* __restrict__ dst,
                               int* __restrict__ wrk, int* __restrict__ colsrc, int E) {
    int e = blockIdx.x * blockDim.x + threadIdx.x;
    if (e >= E) return;
    int pos = atomicAdd(&wrk[dst[e]], 1);
    colsrc[pos] = src[e];
}

// ---------------- CSR aggregate: warp per dst, softmax + head-mean fused -----------------
template<int C>
__global__ void csr_agg_kernel(const int* __restrict__ rp, const int* __restrict__ cs,
                               const float4* __restrict__ ealpha,
                               const uint16_t* __restrict__ xWh,
                               float* __restrict__ outF, int N) {
    constexpr int CPL = C / 32;
    int w = (blockIdx.x * blockDim.x + threadIdx.x) >> 5;
    int lane = threadIdx.x & 31;
    if (w >= N) return;
    int start = __ldg(&rp[w]);
    int end = __ldg(&rp[w + 1]);

    float num[CPL][4];
#pragma unroll
    for (int cc = 0; cc < CPL; cc++)
#pragma unroll
        for (int h = 0; h < 4; h++) num[cc][h] = 0.f;
    float d0 = 0.f, d1 = 0.f, d2 = 0.f, d3 = 0.f;

#pragma unroll 2
    for (int i = start; i < end; i++) {
        int s = __ldg(&cs[i]);
        float4 ea = __ldg(&ealpha[s]);
        d0 += ea.x; d1 += ea.y; d2 += ea.z; d3 += ea.w;
        const uint2* m = (const uint2*)(xWh + (size_t)s * C * 4);
#pragma unroll
        for (int cc = 0; cc < CPL; cc++) {
            uint2 v = __ldg(&m[lane + cc * 32]);
            __half2 p0 = *(__half2*)&v.x;
            __half2 p1 = *(__half2*)&v.y;
            float2 f0 = __half22float2(p0);
            float2 f1 = __half22float2(p1);
            num[cc][0] += ea.x * f0.x;
            num[cc][1] += ea.y * f0.y;
            num[cc][2] += ea.z * f1.x;
            num[cc][3] += ea.w * f1.y;
        }
    }
    float i0 = 0.25f / (d0 + 1e-16f);
    float i1 = 0.25f / (d1 + 1e-16f);
    float i2 = 0.25f / (d2 + 1e-16f);
    float i3 = 0.25f / (d3 + 1e-16f);
#pragma unroll
    for (int cc = 0; cc < CPL; cc++) {
        int c = lane + cc * 32;
        float* o = outF + (size_t)w * C + c;
        *o = *o + num[cc][0] * i0 + num[cc][1] * i1 + num[cc][2] * i2 + num[cc][3] * i3;
    }
}

// ---------------- global mean pool ----------------
__global__ void pool_kernel(const float* __restrict__ h, const int* __restrict__ batch,
                            float* __restrict__ pooled, int N) {
    int g = blockIdx.x;
    int lo = 0, hi = N;
    while (lo < hi) { int mid = (lo + hi) >> 1; if (batch[mid] < g) lo = mid + 1; else hi = mid; }
    int start = lo;
    lo = start; hi = N;
    while (lo < hi) { int mid = (lo + hi) >> 1; if (batch[mid] < g + 1) lo = mid + 1; else hi = mid; }
    int end = lo;
    int t = threadIdx.x;
    int c = t & 63, chunk = t >> 6;
    float acc = 0.f;
    for (int n = start + chunk; n < end; n += 4) acc += h[(size_t)n * 64 + c];
    __shared__ float sh[4][64];
    sh[chunk][c] = acc;
    __syncthreads();
    if (chunk == 0) {
        float s = sh[0][c] + sh[1][c] + sh[2][c] + sh[3][c];
        int cnt = end - start;
        pooled[g * 64 + c] = s / (float)(cnt > 0 ? cnt : 1);
    }
}

// ---------------- classifier + log_softmax ----------------
__global__ void fc_kernel(const float* __restrict__ pooled, const float* __restrict__ Wfc,
                          const float* __restrict__ bfc, float* __restrict__ out) {
    __shared__ float logits[GG][10];
    int t = threadIdx.x;
    if (t < GG * 10) {
        int g = t / 10, o = t % 10;
        float s = bfc[o];
        const float* pr = pooled + g * 64;
        for (int k = 0; k < 64; k++) s += pr[k] * Wfc[k * 10 + o];
        logits[g][o] = s;
    }
    __syncthreads();
    if (t < GG) {
        float mx = -1e30f;
        for (int o = 0; o < 10; o++) mx = fmaxf(mx, logits[t][o]);
        float sum = 0.f;
        for (int o = 0; o < 10; o++) sum += __expf(logits[t][o] - mx);
        float lse = mx + __logf(sum);
        for (int o = 0; o < 10; o++) out[t * 10 + o] = logits[t][o] - lse;
    }
}

// ---------------- launcher ----------------
extern "C" void kernel_launch(void* const* d_in, const int* in_sizes, int n_in,
                              void* d_out, int out_size) {
    const float* x    = (const float*)d_in[0];
    const int*   ei   = (const int*)d_in[1];
    const int*   batch= (const int*)d_in[2];
    const float* Wm1  = (const float*)d_in[3];
    const float* bm1  = (const float*)d_in[4];
    const float* att1 = (const float*)d_in[5];
    const float* Ws1  = (const float*)d_in[6];
    const float* bs1  = (const float*)d_in[7];
    const float* Wm2  = (const float*)d_in[8];
    const float* bm2  = (const float*)d_in[9];
    const float* att2 = (const float*)d_in[10];
    const float* Wm3  = (const float*)d_in[11];
    const float* bm3  = (const float*)d_in[12];
    const float* att3 = (const float*)d_in[13];
    const float* Ws3  = (const float*)d_in[14];
    const float* bs3  = (const float*)d_in[15];
    const float* Wfc  = (const float*)d_in[16];
    const float* bfc  = (const float*)d_in[17];
    float* out = (float*)d_out;

    const int N = NN;
    const int E = in_sizes[1] / 2;
    const int* src = ei;
    const int* dst = ei + E;

    uint16_t* p_xWh; float4 *p_B4, *p_C4, *p_ea;
    float *p_pl, *p_v, *p_Wp, *p_bp;
    int *p_deg, *p_rp, *p_wrk, *p_cs, *p_part;
    cudaGetSymbolAddress((void**)&p_xWh, g_xWh);
    cudaGetSymbolAddress((void**)&p_B4, g_B4);
    cudaGetSymbolAddress((void**)&p_C4, g_C4);
    cudaGetSymbolAddress((void**)&p_ea, g_ealpha);
    cudaGetSymbolAddress((void**)&p_pl, g_pooled);
    cudaGetSymbolAddress((void**)&p_v, g_v);
    cudaGetSymbolAddress((void**)&p_Wp, g_Wp);
    cudaGetSymbolAddress((void**)&p_bp, g_bp);
    cudaGetSymbolAddress((void**)&p_deg, g_deg);
    cudaGetSymbolAddress((void**)&p_rp, g_rowptr);
    cudaGetSymbolAddress((void**)&p_wrk, g_wrk);
    cudaGetSymbolAddress((void**)&p_cs, g_colsrc);
    cudaGetSymbolAddress((void**)&p_part, g_partials);
    float* p_B = (float*)p_B4;
    float* p_C = (float*)p_C4;

    // opt-in to large dynamic smem for both GEMM instantiations (idempotent, non-stream API)
    cudaFuncSetAttribute(gemm_tf32_v2<uint16_t>,
                         cudaFuncAttributeMaxDynamicSharedMemorySize, GEMM_SMEM);
    cudaFuncSetAttribute(gemm_tf32_v2<float>,
                         cudaFuncAttributeMaxDynamicSharedMemorySize, GEMM_SMEM);

    const int rowTiles = (N + 127) / 128;            // 391
    const int alphaBlocks = (N * 32 + 255) / 256;
    const int eBlocks = (E + 255) / 256;
    const int scanBlocks = (N + 511) / 512;
    const int aggBlocks = (N * 32 + 255) / 256;

    // ---------- CSR build (graph shared across all 3 layers) ----------
    cudaMemsetAsync(p_deg, 0, N * sizeof(int));
    count_kernel<<<eBlocks, 256>>>(dst, p_deg, E);
    scan1_kernel<<<scanBlocks, 512>>>(p_deg, p_rp, p_part, N);
    scan_fix_kernel<<<scanBlocks, 512>>>(p_rp, p_wrk, p_part, N, E);
    scatter_kernel<<<eBlocks, 256>>>(src, dst, p_wrk, p_cs, E);

    // ---------- Layer 1: 64 -> 96 ----------
    permw_proj_kernel<<<(64 * 384 + 255) / 256, 256>>>(Wm1, bm1, att1, p_Wp, p_bp, p_v, 64, 96);
    alpha_kernel<<<alphaBlocks, 256>>>(x, p_v, p_ea, N, 64);
    gemm_tf32_v2<uint16_t><<<dim3(3, rowTiles), 256, GEMM_SMEM>>>(x, p_Wp, p_bp, p_xWh, N, 64, 384);
    gemm_tf32_v2<float><<<dim3(1, rowTiles), 256, GEMM_SMEM>>>(x, Ws1, bs1, p_B, N, 64, 96);
    csr_agg_kernel<96><<<aggBlocks, 256>>>(p_rp, p_cs, p_ea, p_xWh, p_B, N);

    // ---------- Layer 2: 96 -> 96 (self = identity, in-place) ----------
    permw_proj_kernel<<<(96 * 384 + 255) / 256, 256>>>(Wm2, bm2, att2, p_Wp, p_bp, p_v, 96, 96);
    alpha_kernel<<<alphaBlocks, 256>>>(p_B, p_v, p_ea, N, 96);
    gemm_tf32_v2<uint16_t><<<dim3(3, rowTiles), 256, GEMM_SMEM>>>(p_B, p_Wp, p_bp, p_xWh, N, 96, 384);
    csr_agg_kernel<96><<<aggBlocks, 256>>>(p_rp, p_cs, p_ea, p_xWh, p_B, N);

    // ---------- Layer 3: 96 -> 64 ----------
    permw_proj_kernel<<<(96 * 256 + 255) / 256, 256>>>(Wm3, bm3, att3, p_Wp, p_bp, p_v, 96, 64);
    alpha_kernel<<<alphaBlocks, 256>>>(p_B, p_v, p_ea, N, 96);
    gemm_tf32_v2<uint16_t><<<dim3(2, rowTiles), 256, GEMM_SMEM>>>(p_B, p_Wp, p_bp, p_xWh, N, 96, 256);
    gemm_tf32_v2<float><<<dim3(1, rowTiles), 256, GEMM_SMEM>>>(p_B, Ws3, bs3, p_C, N, 96, 64);
    csr_agg_kernel<64><<<aggBlocks, 256>>>(p_rp, p_cs, p_ea, p_xWh, p_C, N);

    // ---------- pool + classifier ----------
    pool_kernel<<<GG, 256>>>(p_C, batch, p_pl, N);
    fc_kernel<<<1, 640>>>(p_pl, Wfc, bfc, out);
}